// round 16
// baseline (speedup 1.0000x reference)
#include <cuda_runtime.h>
#include <cuda_fp16.h>
#include <math.h>
#include <stdint.h>

#define NT   8192
#define DD   256
#define FF   8
#define DFE  64
#define DIN  320
#define DR   256
#define EE   8
#define DH   512

// ---------------- device-global scratch ----------------
__device__ int                 g_cnt[EE];
__device__ int                 g_tok[EE * NT];
__device__ float               g_w[EE * NT];
__device__ __align__(16) __half g_xh[NT * DIN];     // fp16 hi of x
__device__ __align__(16) __half g_xl[NT * DIN];     // fp16 lo of x
// pre-transposed n-major fp16 weights
__device__ __align__(16) __half g_B1[EE * 5 * 512 * 64];   // [e][kc=5][n=512][k=64]
__device__ __align__(16) __half g_B2[EE * 8 * 256 * 64];   // [e][kc=8][n=256][k=64]
__device__ __align__(16) __half g_R1h[5 * 256 * 64];       // Wr1 hi [kc=5][n=256][k=64]
__device__ __align__(16) __half g_R1l[5 * 256 * 64];       // Wr1 lo

// ---------------- helpers ----------------
__device__ __forceinline__ float gelu_tanh(float v) {
    float u = 0.7978845608028654f * (v + 0.044715f * v * v * v);
    return 0.5f * v * (1.0f + tanhf(u));
}
__device__ __forceinline__ float gelu_fast(float v) {
    float u = 0.7978845608028654f * (v + 0.044715f * v * v * v);
    return v / (1.0f + __expf(-2.0f * u));
}
__device__ __forceinline__ uint32_t smem_u32(const void* p) {
    uint32_t a;
    asm("{ .reg .u64 t; cvta.to.shared.u64 t, %1; cvt.u32.u64 %0, t; }" : "=r"(a) : "l"(p));
    return a;
}
__device__ __forceinline__ void mma_f16(float* d, const uint32_t* a, const uint32_t* b) {
    asm volatile(
        "mma.sync.aligned.m16n8k16.row.col.f32.f16.f16.f32 "
        "{%0,%1,%2,%3}, {%4,%5,%6,%7}, {%8,%9}, {%0,%1,%2,%3};"
        : "+f"(d[0]), "+f"(d[1]), "+f"(d[2]), "+f"(d[3])
        : "r"(a[0]), "r"(a[1]), "r"(a[2]), "r"(a[3]), "r"(b[0]), "r"(b[1]));
}
__device__ __forceinline__ void ldsm_x4(uint32_t* r, uint32_t a) {
    asm volatile("ldmatrix.sync.aligned.m8n8.x4.shared.b16 {%0,%1,%2,%3}, [%4];"
        : "=r"(r[0]), "=r"(r[1]), "=r"(r[2]), "=r"(r[3]) : "r"(a));
}
__device__ __forceinline__ void cp16(uint32_t dst, const void* src) {
    asm volatile("cp.async.cg.shared.global [%0], [%1], 16;" :: "r"(dst), "l"(src));
}
__device__ __forceinline__ void cp_commit() {
    asm volatile("cp.async.commit_group;" ::: "memory");
}
__device__ __forceinline__ void cp_wait1() {
    asm volatile("cp.async.wait_group 1;" ::: "memory");
}

// ---------------- K1: build x (fp16 hi/lo) + zero out + counter reset ----------------
__global__ void k_build_x(const float* __restrict__ hidden,
                          const float* __restrict__ feat,
                          const float* __restrict__ Wf,
                          const float* __restrict__ bf,
                          float* __restrict__ out) {
    int tok = blockIdx.x;
    int t = threadIdx.x;
    if (blockIdx.x == 0 && t < EE) g_cnt[t] = 0;
    float v;
    if (t < DD) {
        v = hidden[tok * DD + t];
        out[(size_t)tok * DD + t] = 0.f;   // zero stage_delta region
    } else {
        int j = t - DD;
        float acc = bf[j];
#pragma unroll
        for (int k = 0; k < FF; k++) acc += feat[tok * FF + k] * Wf[k * DFE + j];
        v = acc;
    }
    __half h = __float2half_rn(v);
    g_xh[tok * DIN + t] = h;
    g_xl[tok * DIN + t] = __float2half_rn(v - __half2float(h));
}

// ---------------- K2: weight prep (transpose to n-major fp16; Wr1 hi/lo) ------------
__global__ void k_prep(const float* __restrict__ We1, const float* __restrict__ We2,
                       const float* __restrict__ Wr1) {
    __shared__ float tile[64][65];
    int bx = blockIdx.x;
    int tid = threadIdx.x;
    if (bx < 320) {
        int hb = bx & 7, kc = (bx >> 3) % 5, e = bx / 40;
#pragma unroll
        for (int i = 0; i < 16; i++) {
            int li = i * 256 + tid;
            int ki = li >> 6, hi = li & 63;
            tile[ki][hi] = We1[((size_t)e * DIN + kc * 64 + ki) * DH + hb * 64 + hi];
        }
        __syncthreads();
#pragma unroll
        for (int i = 0; i < 16; i++) {
            int li = i * 256 + tid;
            int kk = li & 63, hr = li >> 6;
            size_t dst = (((size_t)(e * 5 + kc) * 512) + hb * 64 + hr) * 64 + kk;
            g_B1[dst] = __float2half_rn(tile[kk][hr]);
        }
    } else if (bx < 576) {
        int b2 = bx - 320;
        int ob = b2 & 3, kc = (b2 >> 2) & 7, e = b2 >> 5;
#pragma unroll
        for (int i = 0; i < 16; i++) {
            int li = i * 256 + tid;
            int ki = li >> 6, oi = li & 63;
            tile[ki][oi] = We2[((size_t)e * DH + kc * 64 + ki) * DD + ob * 64 + oi];
        }
        __syncthreads();
#pragma unroll
        for (int i = 0; i < 16; i++) {
            int li = i * 256 + tid;
            int kk = li & 63, orr = li >> 6;
            size_t dst = (((size_t)(e * 8 + kc) * 256) + ob * 64 + orr) * 64 + kk;
            g_B2[dst] = __float2half_rn(tile[kk][orr]);
        }
    } else {
        int b3 = bx - 576;          // 20 blocks: nb(4) x kc(5)
        int nb = b3 & 3, kc = b3 >> 2;
#pragma unroll
        for (int i = 0; i < 16; i++) {
            int li = i * 256 + tid;
            int ki = li >> 6, ni = li & 63;
            tile[ki][ni] = Wr1[(kc * 64 + ki) * DR + nb * 64 + ni];
        }
        __syncthreads();
#pragma unroll
        for (int i = 0; i < 16; i++) {
            int li = i * 256 + tid;
            int kk = li & 63, nr = li >> 6;
            float v = tile[kk][nr];
            __half h = __float2half_rn(v);
            __half l = __float2half_rn(v - __half2float(h));
            size_t dst = ((size_t)kc * 256 + nb * 64 + nr) * 64 + kk;
            g_R1h[dst] = h;
            g_R1l[dst] = l;
        }
    }
}

// ---------------- K3: router — 512 threads, HMMA 3-term GEMM1, fp32 GEMM2 ----------
#define RT_AL   41984
#define RT_B    83968
#define RT_SMEM (83968 + 3 * 36864)

__global__ __launch_bounds__(512, 1) void k_router_mma(
    const float* __restrict__ br1,
    const float* __restrict__ Wr2, const float* __restrict__ br2,
    float* __restrict__ out) {
    extern __shared__ char smraw[];
    uint32_t smb = smem_u32(smraw);
    float* smf = (float*)smraw;

    int tid = threadIdx.x, wid = tid >> 5, lane = tid & 31;
    int base = blockIdx.x * 64;
    int wm = wid & 1, wn = wid >> 1, lq = lane >> 2, lr = lane & 3;

    // stage A: x hi/lo for 64 tokens
    {
        int row = tid >> 3, oct = tid & 7;
        const char* sh = (const char*)(g_xh + (size_t)(base + row) * DIN);
        const char* sl = (const char*)(g_xl + (size_t)(base + row) * DIN);
        uint32_t dh = smb + (uint32_t)(row * 656);
        uint32_t dl = smb + RT_AL + (uint32_t)(row * 656);
#pragma unroll
        for (int j = 0; j < 5; j++) {
            int g = oct * 5 + j;
            cp16(dh + g * 16, sh + g * 16);
            cp16(dl + g * 16, sl + g * 16);
        }
        cp_commit();
    }
    auto stageB = [&](int c) {
        int kc = c >> 1, nc = c & 1;
        uint32_t b = smb + RT_B + (uint32_t)(c % 3) * 36864;
        const char* Bh = (const char*)(g_R1h + ((size_t)kc * 256 + nc * 128) * 64);
        const char* Bl = (const char*)(g_R1l + ((size_t)kc * 256 + nc * 128) * 64);
#pragma unroll
        for (int i4 = 0; i4 < 2; i4++) {
            int idx = tid + i4 * 512;
            int r = idx >> 3, su = idx & 7;
            cp16(b + (uint32_t)(r * 144 + su * 16), Bh + r * 128 + su * 16);
            cp16(b + 18432 + (uint32_t)(r * 144 + su * 16), Bl + r * 128 + su * 16);
        }
        cp_commit();
    };
    stageB(0);
    stageB(1);

    uint32_t abase = smb + (uint32_t)((wm * 32 + (lane & 15)) * 656 + ((lane >> 4) << 4));
    uint32_t bbase = (uint32_t)((wn * 16 + (lane & 15)) * 144 + ((lane >> 4) << 4));

    float acc[2][2][2][4];   // [nc][mt][nh][j]
#pragma unroll
    for (int nc = 0; nc < 2; nc++)
#pragma unroll
        for (int mt = 0; mt < 2; mt++)
#pragma unroll
            for (int nh = 0; nh < 2; nh++)
#pragma unroll
                for (int j = 0; j < 4; j++) acc[nc][mt][nh][j] = 0.f;

    for (int c = 0; c < 10; c++) {
        int kc = c >> 1, nc = c & 1;
        cp_wait1();
        __syncthreads();
        if (c + 2 < 10) stageB(c + 2); else cp_commit();

        uint32_t bb = smb + RT_B + (uint32_t)(c % 3) * 36864 + bbase;
        uint32_t ab = abase + (uint32_t)(kc * 128);
#pragma unroll
        for (int s = 0; s < 4; s++) {
            uint32_t ah[2][4], al[2][4], bh[4], bl[4];
#pragma unroll
            for (int mt = 0; mt < 2; mt++) {
                uint32_t a = ab + (uint32_t)(mt * 10496 + s * 32);
                ldsm_x4(ah[mt], a);
                ldsm_x4(al[mt], a + RT_AL);
            }
            {
                uint32_t bo = bb + (uint32_t)(s * 32);
                ldsm_x4(bh, bo);
                ldsm_x4(bl, bo + 18432);
            }
            uint32_t bhe[2] = {bh[0], bh[2]}, bho[2] = {bh[1], bh[3]};
            uint32_t ble[2] = {bl[0], bl[2]}, blo[2] = {bl[1], bl[3]};
#pragma unroll
            for (int mt = 0; mt < 2; mt++) {
                mma_f16(acc[nc][mt][0], ah[mt], bhe);
                mma_f16(acc[nc][mt][0], ah[mt], ble);
                mma_f16(acc[nc][mt][0], al[mt], bhe);
                mma_f16(acc[nc][mt][1], ah[mt], bho);
                mma_f16(acc[nc][mt][1], ah[mt], blo);
                mma_f16(acc[nc][mt][1], al[mt], bho);
            }
        }
    }
    __syncthreads();   // all MMAs done; A region reusable

    // GEMM1 epilogue: hr = gelu(acc + br1) -> smem hr[64][264]
#pragma unroll
    for (int nc = 0; nc < 2; nc++)
#pragma unroll
        for (int mt = 0; mt < 2; mt++)
#pragma unroll
            for (int nh = 0; nh < 2; nh++) {
                int col = nc * 128 + wn * 16 + nh * 8 + lr * 2;
                float b0 = br1[col], b1 = br1[col + 1];
#pragma unroll
                for (int h = 0; h < 2; h++) {
                    int row = wm * 32 + mt * 16 + lq + h * 8;
                    smf[row * 264 + col]     = gelu_tanh(acc[nc][mt][nh][2 * h]     + b0);
                    smf[row * 264 + col + 1] = gelu_tanh(acc[nc][mt][nh][2 * h + 1] + b1);
                }
            }
#pragma unroll
    for (int i = 0; i < 4; i++) {
        int idx = tid + i * 512;
        int k = idx >> 3, e = idx & 7;
        smf[17408 + e * 260 + k] = Wr2[k * EE + e];
    }
    __syncthreads();

    // GEMM2: logits (fp32, exact)
    {
        int e = tid & 7, t0 = tid >> 3;
        float a0 = br2[e];
        const float* hr0 = smf + t0 * 264;
        const float* w2  = smf + 17408 + e * 260;
#pragma unroll 8
        for (int k = 0; k < DR; k += 4) {
            float4 w  = *(const float4*)(w2 + k);
            float4 h0 = *(const float4*)(hr0 + k);
            a0 += h0.x * w.x + h0.y * w.y + h0.z * w.z + h0.w * w.w;
        }
        smf[16896 + t0 * 8 + e] = a0;
        float* lo = out + (size_t)NT * DD + (size_t)NT * EE;
        lo[(size_t)(base + t0) * EE + e] = a0;
    }
    __syncthreads();

    // top-2 gating (64 tokens)
    if (tid < 64) {
        int gtok = base + tid;
        float v[EE];
#pragma unroll
        for (int e = 0; e < EE; e++) v[e] = smf[16896 + tid * 8 + e];
        int i0 = 0;
#pragma unroll
        for (int e = 1; e < EE; e++)
            if (v[e] > v[i0]) i0 = e;
        int i1 = (i0 == 0) ? 1 : 0;
#pragma unroll
        for (int e = 0; e < EE; e++) {
            if (e == i0) continue;
            if (v[e] > v[i1]) i1 = e;
        }
        float t  = expf(v[i1] - v[i0]);
        float s  = 1.0f + t;
        float w0 = 1.0f / s;
        float w1 = t / s;
        float* gw = out + (size_t)NT * DD + (size_t)gtok * EE;
#pragma unroll
        for (int e = 0; e < EE; e++)
            gw[e] = (e == i0) ? w0 : ((e == i1) ? w1 : 0.0f);
        int p0 = atomicAdd(&g_cnt[i0], 1);
        g_tok[i0 * NT + p0] = gtok;
        g_w[i0 * NT + p0]   = w0;
        int p1 = atomicAdd(&g_cnt[i1], 1);
        g_tok[i1 * NT + p1] = gtok | (1 << 31);
        g_w[i1 * NT + p1]   = w1;
    }
}

// ---------------- fused expert: M=64, 512 threads, he in smem -----------------------
// smem: A1 [0, 41984) 64x656B ; he [41984, 112640) 64x1104B (552 halves, conflict-free)
//       B ring 3 x 18432 at 112640 ; total 167936
#define F_HE    41984
#define F_B     112640
#define F_SMEM  167936

__global__ __launch_bounds__(512, 1) void k_expert_fused(
    const float* __restrict__ be1, const float* __restrict__ be2,
    float* __restrict__ out) {
    int e = blockIdx.y;
    int cnt = g_cnt[e];
    int base = blockIdx.x * 64;
    if (base >= cnt) return;
    int nrows = min(64, cnt - base);

    extern __shared__ char smraw[];
    uint32_t smb = smem_u32(smraw);

    __shared__ int   s_tok[64];
    __shared__ float s_w[64];

    int tid = threadIdx.x, wid = tid >> 5, lane = tid & 31;
    if (tid < 64) {
        int r = tid;
        int rr = (r < nrows) ? r : 0;
        int ent = g_tok[e * NT + base + rr];
        s_tok[r] = ent & 0x7FFFFFFF;
        s_w[r]   = g_w[e * NT + base + rr];
    }
    __syncthreads();

    int wm = wid & 1, wn = wid >> 1, lq = lane >> 2, lr = lane & 3;

    // stage full A1 (group 0)
    {
        int row = tid >> 3, oct = tid & 7;
        const char* srch = (const char*)(g_xh + (size_t)s_tok[row] * DIN);
        uint32_t dh = smb + (uint32_t)(row * 656);
#pragma unroll
        for (int j = 0; j < 5; j++) {
            int g = oct * 5 + j;
            cp16(dh + g * 16, srch + g * 16);
        }
        cp_commit();
    }
    // unified B stager: c<20 -> B1[nc=c/5][kc=c%5]; c>=20 -> B2[nc2=(c-20)>>3][kcl=(c-20)&7]
    auto stage = [&](int c) {
        const char* src;
        if (c < 20) {
            int nc = c / 5, kc = c - nc * 5;
            src = (const char*)(g_B1 + (((size_t)(e * 5 + kc) * 512) + nc * 128) * 64);
        } else {
            int c2 = c - 20;
            int nc2 = c2 >> 3, kcl = c2 & 7;
            src = (const char*)(g_B2 + (((size_t)(e * 8 + kcl) * 256) + nc2 * 128) * 64);
        }
        uint32_t b = smb + F_B + (uint32_t)(c % 3) * 18432;
#pragma unroll
        for (int i4 = 0; i4 < 2; i4++) {
            int idx = tid + i4 * 512;
            int r = idx >> 3, su = idx & 7;
            cp16(b + (uint32_t)(r * 144 + su * 16), src + r * 128 + su * 16);
        }
        cp_commit();
    };
    stage(0);
    stage(1);

    uint32_t abase1 = smb + (uint32_t)((wm * 32 + (lane & 15)) * 656 + ((lane >> 4) << 4));
    uint32_t abase2 = smb + F_HE + (uint32_t)((wm * 32 + (lane & 15)) * 1104 + ((lane >> 4) << 4));
    uint32_t bbase  = (uint32_t)((wn * 16 + (lane & 15)) * 144 + ((lane >> 4) << 4));

    float acc[2][2][4];   // [mt][nh][j] — reused across phases
    for (int c = 0; c < 36; c++) {
        cp_wait1();
        __syncthreads();
        if (c + 2 < 36) stage(c + 2); else cp_commit();

        uint32_t bb = smb + F_B + (uint32_t)(c % 3) * 18432 + bbase;

        if (c < 20) {
            // ---- layer 1 ----
            int nc = c / 5, kc = c - nc * 5;
            if (kc == 0) {
#pragma unroll
                for (int mt = 0; mt < 2; mt++)
#pragma unroll
                    for (int nh = 0; nh < 2; nh++)
#pragma unroll
                        for (int j = 0; j < 4; j++) acc[mt][nh][j] = 0.f;
            }
            uint32_t ab = abase1 + (uint32_t)(kc * 128);
#pragma unroll
            for (int s = 0; s < 4; s++) {
                uint32_t ah[2][4], bq[4];
#pragma unroll
                for (int mt = 0; mt < 2; mt++)
                    ldsm_x4(ah[mt], ab + (uint32_t)(mt * 10496 + s * 32));
                ldsm_x4(bq, bb + (uint32_t)(s * 32));
                uint32_t bhe[2] = {bq[0], bq[2]}, bho[2] = {bq[1], bq[3]};
#pragma unroll
                for (int mt = 0; mt < 2; mt++) {
                    mma_f16(acc[mt][0], ah[mt], bhe);
                    mma_f16(acc[mt][1], ah[mt], bho);
                }
            }
            if (kc == 4) {
                // bias + gelu -> fp16 he in smem (all rows, no predication)
                const float* b1 = be1 + e * DH + nc * 128;
#pragma unroll
                for (int mt = 0; mt < 2; mt++)
#pragma unroll
                    for (int nh = 0; nh < 2; nh++) {
                        int col = wn * 16 + nh * 8 + lr * 2;
                        float bb0 = b1[col], bb1 = b1[col + 1];
#pragma unroll
                        for (int h = 0; h < 2; h++) {
                            int row = wm * 32 + mt * 16 + lq + h * 8;
                            float v0 = gelu_fast(acc[mt][nh][2 * h]     + bb0);
                            float v1 = gelu_fast(acc[mt][nh][2 * h + 1] + bb1);
                            __half h0 = __float2half_rn(v0), h1 = __float2half_rn(v1);
                            uint32_t ph = (uint32_t)__half_as_ushort(h0) | ((uint32_t)__half_as_ushort(h1) << 16);
                            *(uint32_t*)(smraw + F_HE + row * 1104 + (nc * 128 + col) * 2) = ph;
                        }
                    }
            }
        } else {
            // ---- layer 2 ----
            int c2 = c - 20;
            int nc2 = c2 >> 3, kcl = c2 & 7;
            if (kcl == 0) {
#pragma unroll
                for (int mt = 0; mt < 2; mt++)
#pragma unroll
                    for (int nh = 0; nh < 2; nh++)
#pragma unroll
                        for (int j = 0; j < 4; j++) acc[mt][nh][j] = 0.f;
            }
            uint32_t ab = abase2 + (uint32_t)(kcl * 128);
#pragma unroll
            for (int s = 0; s < 4; s++) {
                uint32_t ah[2][4], bq[4];
#pragma unroll
                for (int mt = 0; mt < 2; mt++)
                    ldsm_x4(ah[mt], ab + (uint32_t)(mt * 17664 + s * 32));
                ldsm_x4(bq, bb + (uint32_t)(s * 32));
                uint32_t bhe[2] = {bq[0], bq[2]}, bho[2] = {bq[1], bq[3]};
#pragma unroll
                for (int mt = 0; mt < 2; mt++) {
                    mma_f16(acc[mt][0], ah[mt], bhe);
                    mma_f16(acc[mt][1], ah[mt], bho);
                }
            }
            if (kcl == 7) {
                // gate-scaled bias add, atomicAdd into out (exactly 2 adds/elem)
                const float* b2 = be2 + e * DD + nc2 * 128;
#pragma unroll
                for (int mt = 0; mt < 2; mt++)
#pragma unroll
                    for (int nh = 0; nh < 2; nh++) {
                        int col = wn * 16 + nh * 8 + lr * 2;
                        float bb0 = b2[col], bb1 = b2[col + 1];
#pragma unroll
                        for (int h = 0; h < 2; h++) {
                            int row = wm * 32 + mt * 16 + lq + h * 8;
                            if (row < nrows) {
                                float wgt = s_w[row];
                                float* dst = out + (size_t)s_tok[row] * DD + nc2 * 128 + col;
                                atomicAdd(dst,     wgt * (acc[mt][nh][2 * h]     + bb0));
                                atomicAdd(dst + 1, wgt * (acc[mt][nh][2 * h + 1] + bb1));
                            }
                        }
                    }
            }
        }
    }
}

// ---------------- launch ----------------
extern "C" void kernel_launch(void* const* d_in, const int* in_sizes, int n_in,
                              void* d_out, int out_size) {
    const float* hidden = (const float*)d_in[0];
    const float* feat   = (const float*)d_in[1];
    const float* Wf     = (const float*)d_in[2];
    const float* bf     = (const float*)d_in[3];
    const float* Wr1    = (const float*)d_in[4];
    const float* br1    = (const float*)d_in[5];
    const float* Wr2    = (const float*)d_in[6];
    const float* br2    = (const float*)d_in[7];
    const float* We1    = (const float*)d_in[8];
    const float* be1    = (const float*)d_in[9];
    const float* We2    = (const float*)d_in[10];
    const float* be2    = (const float*)d_in[11];
    float* out = (float*)d_out;

    cudaFuncSetAttribute(k_router_mma, cudaFuncAttributeMaxDynamicSharedMemorySize, RT_SMEM);
    cudaFuncSetAttribute(k_expert_fused, cudaFuncAttributeMaxDynamicSharedMemorySize, F_SMEM);

    k_build_x<<<NT, DIN>>>(hidden, feat, Wf, bf, out);
    k_prep<<<596, 256>>>(We1, We2, Wr1);
    k_router_mma<<<NT / 64, 512, RT_SMEM>>>(br1, Wr2, br2, out);
    k_expert_fused<<<dim3(128, EE), 512, F_SMEM>>>(be1, be2, out);
}

// round 17
// speedup vs baseline: 1.0925x; 1.0925x over previous
#include <cuda_runtime.h>
#include <cuda_fp16.h>
#include <math.h>
#include <stdint.h>

#define NT   8192
#define DD   256
#define FF   8
#define DFE  64
#define DIN  320
#define DR   256
#define EE   8
#define DH   512

// ---------------- device-global scratch ----------------
__device__ int                 g_cnt[EE];
__device__ int                 g_tok[EE * NT];
__device__ float               g_w[EE * NT];
__device__ __align__(16) __half g_xh[NT * DIN];     // fp16 hi of x
__device__ __align__(16) __half g_xl[NT * DIN];     // fp16 lo of x
__device__ __align__(16) __half g_heh[2 * NT * DH]; // fp16 he
// pre-transposed n-major fp16 weights
__device__ __align__(16) __half g_B1[EE * 5 * 512 * 64];   // [e][kc=5][n=512][k=64]
__device__ __align__(16) __half g_B2[EE * 8 * 256 * 64];   // [e][kc=8][n=256][k=64]
__device__ __align__(16) __half g_R1h[5 * 256 * 64];       // Wr1 hi [kc=5][n=256][k=64]
__device__ __align__(16) __half g_R1l[5 * 256 * 64];       // Wr1 lo

// ---------------- helpers ----------------
__device__ __forceinline__ float gelu_tanh(float v) {
    float u = 0.7978845608028654f * (v + 0.044715f * v * v * v);
    return 0.5f * v * (1.0f + tanhf(u));
}
__device__ __forceinline__ float gelu_fast(float v) {
    float u = 0.7978845608028654f * (v + 0.044715f * v * v * v);
    return v / (1.0f + __expf(-2.0f * u));
}
__device__ __forceinline__ uint32_t smem_u32(const void* p) {
    uint32_t a;
    asm("{ .reg .u64 t; cvta.to.shared.u64 t, %1; cvt.u32.u64 %0, t; }" : "=r"(a) : "l"(p));
    return a;
}
__device__ __forceinline__ void mma_f16(float* d, const uint32_t* a, const uint32_t* b) {
    asm volatile(
        "mma.sync.aligned.m16n8k16.row.col.f32.f16.f16.f32 "
        "{%0,%1,%2,%3}, {%4,%5,%6,%7}, {%8,%9}, {%0,%1,%2,%3};"
        : "+f"(d[0]), "+f"(d[1]), "+f"(d[2]), "+f"(d[3])
        : "r"(a[0]), "r"(a[1]), "r"(a[2]), "r"(a[3]), "r"(b[0]), "r"(b[1]));
}
__device__ __forceinline__ void ldsm_x4(uint32_t* r, uint32_t a) {
    asm volatile("ldmatrix.sync.aligned.m8n8.x4.shared.b16 {%0,%1,%2,%3}, [%4];"
        : "=r"(r[0]), "=r"(r[1]), "=r"(r[2]), "=r"(r[3]) : "r"(a));
}
__device__ __forceinline__ void cp16(uint32_t dst, const void* src) {
    asm volatile("cp.async.cg.shared.global [%0], [%1], 16;" :: "r"(dst), "l"(src));
}
__device__ __forceinline__ void cp_commit() {
    asm volatile("cp.async.commit_group;" ::: "memory");
}
__device__ __forceinline__ void cp_wait1() {
    asm volatile("cp.async.wait_group 1;" ::: "memory");
}

// ---------------- K1: fused pre-pass: build x + zero out + weight prep ----------------
// blocks [0, NT): build x (fp16 hi/lo), zero out, reset counters (block 0)
// blocks [NT, NT+596): weight transpose/split (320-thread strided loops)
__global__ void k_pre(const float* __restrict__ hidden,
                      const float* __restrict__ feat,
                      const float* __restrict__ Wf,
                      const float* __restrict__ bf,
                      const float* __restrict__ We1,
                      const float* __restrict__ We2,
                      const float* __restrict__ Wr1,
                      float* __restrict__ out) {
    __shared__ float tile[64][65];
    int tid = threadIdx.x;
    if (blockIdx.x < NT) {
        int tok = blockIdx.x;
        if (tok == 0 && tid < EE) g_cnt[tid] = 0;
        float v;
        if (tid < DD) {
            v = hidden[tok * DD + tid];
            out[(size_t)tok * DD + tid] = 0.f;
        } else {
            int j = tid - DD;
            float acc = bf[j];
#pragma unroll
            for (int k = 0; k < FF; k++) acc += feat[tok * FF + k] * Wf[k * DFE + j];
            v = acc;
        }
        __half h = __float2half_rn(v);
        g_xh[tok * DIN + tid] = h;
        g_xl[tok * DIN + tid] = __float2half_rn(v - __half2float(h));
        return;
    }
    int bx = blockIdx.x - NT;
    if (bx < 320) {
        int hb = bx & 7, kc = (bx >> 3) % 5, e = bx / 40;
        for (int idx = tid; idx < 4096; idx += 320) {
            int ki = idx >> 6, hi = idx & 63;
            tile[ki][hi] = We1[((size_t)e * DIN + kc * 64 + ki) * DH + hb * 64 + hi];
        }
        __syncthreads();
        for (int idx = tid; idx < 4096; idx += 320) {
            int kk = idx & 63, hr = idx >> 6;
            size_t dst = (((size_t)(e * 5 + kc) * 512) + hb * 64 + hr) * 64 + kk;
            g_B1[dst] = __float2half_rn(tile[kk][hr]);
        }
    } else if (bx < 576) {
        int b2 = bx - 320;
        int ob = b2 & 3, kc = (b2 >> 2) & 7, e = b2 >> 5;
        for (int idx = tid; idx < 4096; idx += 320) {
            int ki = idx >> 6, oi = idx & 63;
            tile[ki][oi] = We2[((size_t)e * DH + kc * 64 + ki) * DD + ob * 64 + oi];
        }
        __syncthreads();
        for (int idx = tid; idx < 4096; idx += 320) {
            int kk = idx & 63, orr = idx >> 6;
            size_t dst = (((size_t)(e * 8 + kc) * 256) + ob * 64 + orr) * 64 + kk;
            g_B2[dst] = __float2half_rn(tile[kk][orr]);
        }
    } else {
        int b3 = bx - 576;          // 20 blocks: nb(4) x kc(5)
        int nb = b3 & 3, kc = b3 >> 2;
        for (int idx = tid; idx < 4096; idx += 320) {
            int ki = idx >> 6, ni = idx & 63;
            tile[ki][ni] = Wr1[(kc * 64 + ki) * DR + nb * 64 + ni];
        }
        __syncthreads();
        for (int idx = tid; idx < 4096; idx += 320) {
            int kk = idx & 63, nr = idx >> 6;
            float v = tile[kk][nr];
            __half h = __float2half_rn(v);
            __half l = __float2half_rn(v - __half2float(h));
            size_t dst = ((size_t)kc * 256 + nb * 64 + nr) * 64 + kk;
            g_R1h[dst] = h;
            g_R1l[dst] = l;
        }
    }
}

// ---------------- K3: router — 512 threads, HMMA 3-term GEMM1, fp32 GEMM2 ----------
#define RT_AL   41984
#define RT_B    83968
#define RT_SMEM (83968 + 3 * 36864)

__global__ __launch_bounds__(512, 1) void k_router_mma(
    const float* __restrict__ br1,
    const float* __restrict__ Wr2, const float* __restrict__ br2,
    float* __restrict__ out) {
    extern __shared__ char smraw[];
    uint32_t smb = smem_u32(smraw);
    float* smf = (float*)smraw;

    int tid = threadIdx.x, wid = tid >> 5, lane = tid & 31;
    int base = blockIdx.x * 64;
    int wm = wid & 1, wn = wid >> 1, lq = lane >> 2, lr = lane & 3;

    // stage A: x hi/lo for 64 tokens
    {
        int row = tid >> 3, oct = tid & 7;
        const char* sh = (const char*)(g_xh + (size_t)(base + row) * DIN);
        const char* sl = (const char*)(g_xl + (size_t)(base + row) * DIN);
        uint32_t dh = smb + (uint32_t)(row * 656);
        uint32_t dl = smb + RT_AL + (uint32_t)(row * 656);
#pragma unroll
        for (int j = 0; j < 5; j++) {
            int g = oct * 5 + j;
            cp16(dh + g * 16, sh + g * 16);
            cp16(dl + g * 16, sl + g * 16);
        }
        cp_commit();
    }
    auto stageB = [&](int c) {
        int kc = c >> 1, nc = c & 1;
        uint32_t b = smb + RT_B + (uint32_t)(c % 3) * 36864;
        const char* Bh = (const char*)(g_R1h + ((size_t)kc * 256 + nc * 128) * 64);
        const char* Bl = (const char*)(g_R1l + ((size_t)kc * 256 + nc * 128) * 64);
#pragma unroll
        for (int i4 = 0; i4 < 2; i4++) {
            int idx = tid + i4 * 512;
            int r = idx >> 3, su = idx & 7;
            cp16(b + (uint32_t)(r * 144 + su * 16), Bh + r * 128 + su * 16);
            cp16(b + 18432 + (uint32_t)(r * 144 + su * 16), Bl + r * 128 + su * 16);
        }
        cp_commit();
    };
    stageB(0);
    stageB(1);

    uint32_t abase = smb + (uint32_t)((wm * 32 + (lane & 15)) * 656 + ((lane >> 4) << 4));
    uint32_t bbase = (uint32_t)((wn * 16 + (lane & 15)) * 144 + ((lane >> 4) << 4));

    float acc[2][2][2][4];   // [nc][mt][nh][j]
#pragma unroll
    for (int nc = 0; nc < 2; nc++)
#pragma unroll
        for (int mt = 0; mt < 2; mt++)
#pragma unroll
            for (int nh = 0; nh < 2; nh++)
#pragma unroll
                for (int j = 0; j < 4; j++) acc[nc][mt][nh][j] = 0.f;

    for (int c = 0; c < 10; c++) {
        int kc = c >> 1, nc = c & 1;
        cp_wait1();
        __syncthreads();
        if (c + 2 < 10) stageB(c + 2); else cp_commit();

        uint32_t bb = smb + RT_B + (uint32_t)(c % 3) * 36864 + bbase;
        uint32_t ab = abase + (uint32_t)(kc * 128);
#pragma unroll
        for (int s = 0; s < 4; s++) {
            uint32_t ah[2][4], al[2][4], bh[4], bl[4];
#pragma unroll
            for (int mt = 0; mt < 2; mt++) {
                uint32_t a = ab + (uint32_t)(mt * 10496 + s * 32);
                ldsm_x4(ah[mt], a);
                ldsm_x4(al[mt], a + RT_AL);
            }
            {
                uint32_t bo = bb + (uint32_t)(s * 32);
                ldsm_x4(bh, bo);
                ldsm_x4(bl, bo + 18432);
            }
            uint32_t bhe[2] = {bh[0], bh[2]}, bho[2] = {bh[1], bh[3]};
            uint32_t ble[2] = {bl[0], bl[2]}, blo[2] = {bl[1], bl[3]};
#pragma unroll
            for (int mt = 0; mt < 2; mt++) {
                mma_f16(acc[nc][mt][0], ah[mt], bhe);
                mma_f16(acc[nc][mt][0], ah[mt], ble);
                mma_f16(acc[nc][mt][0], al[mt], bhe);
                mma_f16(acc[nc][mt][1], ah[mt], bho);
                mma_f16(acc[nc][mt][1], ah[mt], blo);
                mma_f16(acc[nc][mt][1], al[mt], bho);
            }
        }
    }
    __syncthreads();   // all MMAs done; A region reusable

    // GEMM1 epilogue: hr = gelu(acc + br1) -> smem hr[64][264]
#pragma unroll
    for (int nc = 0; nc < 2; nc++)
#pragma unroll
        for (int mt = 0; mt < 2; mt++)
#pragma unroll
            for (int nh = 0; nh < 2; nh++) {
                int col = nc * 128 + wn * 16 + nh * 8 + lr * 2;
                float b0 = br1[col], b1 = br1[col + 1];
#pragma unroll
                for (int h = 0; h < 2; h++) {
                    int row = wm * 32 + mt * 16 + lq + h * 8;
                    smf[row * 264 + col]     = gelu_tanh(acc[nc][mt][nh][2 * h]     + b0);
                    smf[row * 264 + col + 1] = gelu_tanh(acc[nc][mt][nh][2 * h + 1] + b1);
                }
            }
#pragma unroll
    for (int i = 0; i < 4; i++) {
        int idx = tid + i * 512;
        int k = idx >> 3, e = idx & 7;
        smf[17408 + e * 260 + k] = Wr2[k * EE + e];
    }
    __syncthreads();

    // GEMM2: logits (fp32, exact)
    {
        int e = tid & 7, t0 = tid >> 3;
        float a0 = br2[e];
        const float* hr0 = smf + t0 * 264;
        const float* w2  = smf + 17408 + e * 260;
#pragma unroll 8
        for (int k = 0; k < DR; k += 4) {
            float4 w  = *(const float4*)(w2 + k);
            float4 h0 = *(const float4*)(hr0 + k);
            a0 += h0.x * w.x + h0.y * w.y + h0.z * w.z + h0.w * w.w;
        }
        smf[16896 + t0 * 8 + e] = a0;
        float* lo = out + (size_t)NT * DD + (size_t)NT * EE;
        lo[(size_t)(base + t0) * EE + e] = a0;
    }
    __syncthreads();

    // top-2 gating (64 tokens)
    if (tid < 64) {
        int gtok = base + tid;
        float v[EE];
#pragma unroll
        for (int e = 0; e < EE; e++) v[e] = smf[16896 + tid * 8 + e];
        int i0 = 0;
#pragma unroll
        for (int e = 1; e < EE; e++)
            if (v[e] > v[i0]) i0 = e;
        int i1 = (i0 == 0) ? 1 : 0;
#pragma unroll
        for (int e = 0; e < EE; e++) {
            if (e == i0) continue;
            if (v[e] > v[i1]) i1 = e;
        }
        float t  = expf(v[i1] - v[i0]);
        float s  = 1.0f + t;
        float w0 = 1.0f / s;
        float w1 = t / s;
        float* gw = out + (size_t)NT * DD + (size_t)gtok * EE;
#pragma unroll
        for (int e = 0; e < EE; e++)
            gw[e] = (e == i0) ? w0 : ((e == i1) ? w1 : 0.0f);
        int p0 = atomicAdd(&g_cnt[i0], 1);
        g_tok[i0 * NT + p0] = gtok;
        g_w[i0 * NT + p0]   = w0;
        int p1 = atomicAdd(&g_cnt[i1], 1);
        g_tok[i1 * NT + p1] = gtok | (1 << 31);
        g_w[i1 * NT + p1]   = w1;
    }
}

// ---------------- expert layer 1: M=64, 256 thr, 2 CTA/SM, A resident ---------------
#define E1_A    0
#define E1_B    41984
#define E1_SMEM 97280

__global__ __launch_bounds__(256, 2) void k_expert1(const float* __restrict__ be1) {
    int e = blockIdx.y;
    int cnt = g_cnt[e];
    int base = blockIdx.x * 64;
    if (base >= cnt) return;
    int nrows = min(64, cnt - base);

    extern __shared__ char smraw[];
    uint32_t smb = smem_u32(smraw);

    __shared__ int s_tok[64];
    __shared__ int s_dst[64];

    int tid = threadIdx.x, wid = tid >> 5, lane = tid & 31;
    if (tid < 64) {
        int r = tid;
        int rr = (r < nrows) ? r : 0;
        int ent = g_tok[e * NT + base + rr];
        int tok = ent & 0x7FFFFFFF;
        s_tok[r] = tok;
        s_dst[r] = (r < nrows) ? (int)((((unsigned)ent) >> 31) * NT + tok) : -1;
    }
    __syncthreads();

    int wm = wid & 1, wn = wid >> 1, lq = lane >> 2, lr = lane & 3;

    {
        int row = tid >> 2, q = tid & 3;
        const char* srch = (const char*)(g_xh + (size_t)s_tok[row] * DIN);
        uint32_t dh = smb + E1_A + (uint32_t)(row * 656);
#pragma unroll
        for (int j = 0; j < 10; j++) {
            int g = q * 10 + j;
            cp16(dh + g * 16, srch + g * 16);
        }
        cp_commit();
    }
    auto stageB = [&](int c) {
        int nc = c / 5, kc = c - nc * 5;
        uint32_t b = smb + E1_B + (uint32_t)(c % 3) * 18432;
        const char* B1 = (const char*)(g_B1 + (((size_t)(e * 5 + kc) * 512) + nc * 128) * 64);
#pragma unroll
        for (int i4 = 0; i4 < 4; i4++) {
            int idx = tid + i4 * 256;
            int r = idx >> 3, su = idx & 7;
            cp16(b + (uint32_t)(r * 144 + su * 16), B1 + r * 128 + su * 16);
        }
        cp_commit();
    };
    stageB(0);
    stageB(1);

    uint32_t abase = smb + E1_A + (uint32_t)((wm * 32 + (lane & 15)) * 656 + ((lane >> 4) << 4));
    uint32_t bbase = (uint32_t)((wn * 32 + (lane & 15)) * 144 + ((lane >> 4) << 4));

    float acc[2][4][4];
    for (int c = 0; c < 20; c++) {
        int nc = c / 5, kc = c - nc * 5;
        cp_wait1();
        __syncthreads();
        if (c + 2 < 20) stageB(c + 2); else cp_commit();

        if (kc == 0) {
#pragma unroll
            for (int mt = 0; mt < 2; mt++)
#pragma unroll
                for (int nt = 0; nt < 4; nt++)
#pragma unroll
                    for (int j = 0; j < 4; j++) acc[mt][nt][j] = 0.f;
        }
        uint32_t bb = smb + E1_B + (uint32_t)(c % 3) * 18432 + bbase;
        uint32_t ab = abase + (uint32_t)(kc * 128);
#pragma unroll
        for (int s = 0; s < 4; s++) {
            uint32_t ah[2][4], bq[2][4];
#pragma unroll
            for (int mt = 0; mt < 2; mt++)
                ldsm_x4(ah[mt], ab + (uint32_t)(mt * 10496 + s * 32));
#pragma unroll
            for (int g = 0; g < 2; g++)
                ldsm_x4(bq[g], bb + (uint32_t)(g * 2304 + s * 32));
#pragma unroll
            for (int g = 0; g < 2; g++) {
                uint32_t bhe[2] = {bq[g][0], bq[g][2]}, bho[2] = {bq[g][1], bq[g][3]};
#pragma unroll
                for (int mt = 0; mt < 2; mt++) {
                    mma_f16(acc[mt][2 * g],     ah[mt], bhe);
                    mma_f16(acc[mt][2 * g + 1], ah[mt], bho);
                }
            }
        }

        if (kc == 4) {
            const float* b1 = be1 + e * DH + nc * 128;
#pragma unroll
            for (int mt = 0; mt < 2; mt++)
#pragma unroll
                for (int nt = 0; nt < 4; nt++) {
                    int col = wn * 32 + nt * 8 + lr * 2;
                    float bb0 = b1[col], bb1 = b1[col + 1];
#pragma unroll
                    for (int h = 0; h < 2; h++) {
                        int row = wm * 32 + mt * 16 + lq + h * 8;
                        int dst = s_dst[row];
                        if (dst >= 0) {
                            float v0 = gelu_fast(acc[mt][nt][2 * h]     + bb0);
                            float v1 = gelu_fast(acc[mt][nt][2 * h + 1] + bb1);
                            __half h0 = __float2half_rn(v0), h1 = __float2half_rn(v1);
                            uint32_t ph = (uint32_t)__half_as_ushort(h0) | ((uint32_t)__half_as_ushort(h1) << 16);
                            size_t widx = ((size_t)dst * DH + nc * 128 + col) >> 1;
                            ((uint32_t*)g_heh)[widx] = ph;
                        }
                    }
                }
        }
    }
}

// ---------------- expert layer 2: M=64, 256 thr, 2 CTA/SM, atomic epilogue ---------
#define E2_A    0
#define E2_B    33792
#define E2_SMEM 89088

__global__ __launch_bounds__(256, 2) void k_expert2(const float* __restrict__ be2,
                                                    float* __restrict__ out) {
    int e = blockIdx.y;
    int cnt = g_cnt[e];
    int base = blockIdx.x * 64;
    if (base >= cnt) return;
    int nrows = min(64, cnt - base);

    extern __shared__ char smraw[];
    uint32_t smb = smem_u32(smraw);

    __shared__ int   s_row[64];
    __shared__ int   s_tk[64];
    __shared__ float s_w[64];

    int tid = threadIdx.x, wid = tid >> 5, lane = tid & 31;
    if (tid < 64) {
        int r = tid;
        int rr = (r < nrows) ? r : 0;
        int ent = g_tok[e * NT + base + rr];
        int tok = ent & 0x7FFFFFFF;
        s_row[r] = (int)((((unsigned)ent) >> 31) * NT + tok);
        s_tk[r]  = (r < nrows) ? tok : -1;
        s_w[r]   = g_w[e * NT + base + rr];
    }
    __syncthreads();

    int wm = wid & 1, wn = wid >> 1, lq = lane >> 2, lr = lane & 3;

    uint32_t abase = smb + E2_A + (uint32_t)((wm * 32 + (lane & 15)) * 528 + ((lane >> 4) << 4));
    uint32_t bbase = (uint32_t)((wn * 32 + (lane & 15)) * 144 + ((lane >> 4) << 4));

    auto stageB = [&](int cgl) {
        int j = cgl & 7, kh = cgl >> 3;
        int nc = j >> 2, kcl = j & 3;
        int kc = kh * 4 + kcl;
        uint32_t b = smb + E2_B + (uint32_t)(cgl % 3) * 18432;
        const char* B2 = (const char*)(g_B2 + (((size_t)(e * 8 + kc) * 256) + nc * 128) * 64);
#pragma unroll
        for (int i4 = 0; i4 < 4; i4++) {
            int idx = tid + i4 * 256;
            int r = idx >> 3, su = idx & 7;
            cp16(b + (uint32_t)(r * 144 + su * 16), B2 + r * 128 + su * 16);
        }
        cp_commit();
    };

    float acc[2][2][4][4];
#pragma unroll
    for (int nc = 0; nc < 2; nc++)
#pragma unroll
        for (int mt = 0; mt < 2; mt++)
#pragma unroll
            for (int nt = 0; nt < 4; nt++)
#pragma unroll
                for (int j = 0; j < 4; j++) acc[nc][mt][nt][j] = 0.f;

    for (int kh = 0; kh < 2; kh++) {
        __syncthreads();
        {
            int row = tid >> 2, q = tid & 3;
            const char* srch = (const char*)(g_heh + (size_t)s_row[row] * DH + kh * 256);
            uint32_t dh = smb + E2_A + (uint32_t)(row * 528);
#pragma unroll
            for (int j = 0; j < 8; j++) {
                int g = q * 8 + j;
                cp16(dh + g * 16, srch + g * 16);
            }
            cp_commit();
        }
        stageB(kh * 8);
        stageB(kh * 8 + 1);

        for (int j = 0; j < 8; j++) {
            int cgl = kh * 8 + j;
            int nc = j >> 2, kcl = j & 3;
            cp_wait1();
            __syncthreads();
            if (j + 2 < 8) stageB(cgl + 2); else cp_commit();

            uint32_t bb = smb + E2_B + (uint32_t)(cgl % 3) * 18432 + bbase;
            uint32_t ab = abase + (uint32_t)(kcl * 128);
#pragma unroll
            for (int s = 0; s < 4; s++) {
                uint32_t ah[2][4], bq[2][4];
#pragma unroll
                for (int mt = 0; mt < 2; mt++)
                    ldsm_x4(ah[mt], ab + (uint32_t)(mt * 8448 + s * 32));
#pragma unroll
                for (int g = 0; g < 2; g++)
                    ldsm_x4(bq[g], bb + (uint32_t)(g * 2304 + s * 32));
#pragma unroll
                for (int g = 0; g < 2; g++) {
                    uint32_t bhe[2] = {bq[g][0], bq[g][2]}, bho[2] = {bq[g][1], bq[g][3]};
#pragma unroll
                    for (int mt = 0; mt < 2; mt++) {
                        mma_f16(acc[nc][mt][2 * g],     ah[mt], bhe);
                        mma_f16(acc[nc][mt][2 * g + 1], ah[mt], bho);
                    }
                }
            }
        }
    }

    // epilogue: gate-scaled bias add, atomicAdd into out (exactly 2 adds/elem)
#pragma unroll
    for (int nc = 0; nc < 2; nc++) {
        const float* b2 = be2 + e * DD + nc * 128;
#pragma unroll
        for (int mt = 0; mt < 2; mt++)
#pragma unroll
            for (int nt = 0; nt < 4; nt++) {
                int col = wn * 32 + nt * 8 + lr * 2;
                float bb0 = b2[col], bb1 = b2[col + 1];
#pragma unroll
                for (int h = 0; h < 2; h++) {
                    int row = wm * 32 + mt * 16 + lq + h * 8;
                    int tk = s_tk[row];
                    if (tk >= 0) {
                        float wgt = s_w[row];
                        float* dst = out + (size_t)tk * DD + nc * 128 + col;
                        atomicAdd(dst,     wgt * (acc[nc][mt][nt][2 * h]     + bb0));
                        atomicAdd(dst + 1, wgt * (acc[nc][mt][nt][2 * h + 1] + bb1));
                    }
                }
            }
    }
}

// ---------------- launch ----------------
extern "C" void kernel_launch(void* const* d_in, const int* in_sizes, int n_in,
                              void* d_out, int out_size) {
    const float* hidden = (const float*)d_in[0];
    const float* feat   = (const float*)d_in[1];
    const float* Wf     = (const float*)d_in[2];
    const float* bf     = (const float*)d_in[3];
    const float* Wr1    = (const float*)d_in[4];
    const float* br1    = (const float*)d_in[5];
    const float* Wr2    = (const float*)d_in[6];
    const float* br2    = (const float*)d_in[7];
    const float* We1    = (const float*)d_in[8];
    const float* be1    = (const float*)d_in[9];
    const float* We2    = (const float*)d_in[10];
    const float* be2    = (const float*)d_in[11];
    float* out = (float*)d_out;

    cudaFuncSetAttribute(k_router_mma, cudaFuncAttributeMaxDynamicSharedMemorySize, RT_SMEM);
    cudaFuncSetAttribute(k_expert1, cudaFuncAttributeMaxDynamicSharedMemorySize, E1_SMEM);
    cudaFuncSetAttribute(k_expert2, cudaFuncAttributeMaxDynamicSharedMemorySize, E2_SMEM);

    k_pre<<<NT + 596, DIN>>>(hidden, feat, Wf, bf, We1, We2, Wr1, out);
    k_router_mma<<<NT / 64, 512, RT_SMEM>>>(br1, Wr2, br2, out);
    k_expert1<<<dim3(128, EE), 256, E1_SMEM>>>(be1);
    k_expert2<<<dim3(128, EE), 256, E2_SMEM>>>(be2, out);
}